// round 14
// baseline (speedup 1.0000x reference)
#include <cuda_runtime.h>
#include <cuda_fp16.h>
#include <cstdint>

// 3-layer GCN, bucket-grouped aggregation, fp16 message payloads.
//   ht = (hW)*isq per node (fp16);  acc[d] = ht[d] + sum_{s->d} ht[s] (fp32);
//   next layer input = relu(isq*acc + b). One edge pass builds per-dst buckets.
// GEMM1: K split across 4 CTAs (fp32 partial slices, no atomics), cp.async
// double-buffered x tiles, k-pair FFMA2; combine kernel sums slices -> ht1.
// edge_index arrives as int32 (JAX x64-disabled demotes int64).

#define GN 100000
#define GE 3200000
#define GK 512
#define GC 16
#define CAP 128      // bucket slots per node; P(deg>128) ~ 1e-60

#define KS 4         // K slices (CTAs per row tile)
#define ROWS_B 64    // rows per gemm CTA
#define KPER (GK / KS)      // 128 k per CTA
#define KCH 64              // k per staged chunk (2 chunks per CTA)
#define XS_F (ROWS_B * KCH) // 4096 floats per buffer
#define WT_P 68             // u64 pitch per channel (64 kpairs + pad, 16B-mult)

// ---------------- scratch (static device globals) ----------------------------
__device__ __align__(256) float  g_isq[GN];
__device__ __align__(256) __half g_ht1[GN * GC];
__device__ __align__(256) __half g_ht2[GN * GC];
__device__ __align__(256) float  g_ht3[GN];
__device__ __align__(256) int    g_cnt[GN];
__device__ __align__(256) int    g_bucket[(size_t)GN * CAP];   // 51.2 MB
__device__ __align__(256) float  g_partf[(size_t)KS * GN * GC]; // 25.6 MB

// ---------------- helpers -----------------------------------------------------
__device__ __forceinline__ unsigned long long ffma2(unsigned long long a,
                                                    unsigned long long b,
                                                    unsigned long long c) {
    unsigned long long d;
    asm("fma.rn.f32x2 %0, %1, %2, %3;" : "=l"(d) : "l"(a), "l"(b), "l"(c));
    return d;
}
__device__ __forceinline__ unsigned long long addf2(unsigned long long a,
                                                    unsigned long long b) {
    unsigned long long d;
    asm("add.rn.f32x2 %0, %1, %2;" : "=l"(d) : "l"(a), "l"(b));
    return d;
}
__device__ __forceinline__ void cp_async16(uint32_t dst, const void* src) {
    asm volatile("cp.async.cg.shared.global [%0], [%1], 16;"
                 :: "r"(dst), "l"(src) : "memory");
}
__device__ __forceinline__ float4 gat4(const uint2* __restrict__ htp, int s, int q) {
    uint2 u = __ldg(htp + (size_t)s * 4 + q);
    __half2 h0 = *(__half2*)&u.x;
    __half2 h1 = *(__half2*)&u.y;
    float2 a = __half22float2(h0), b = __half22float2(h1);
    return make_float4(a.x, a.y, b.x, b.y);
}

// ---------------- prep -------------------------------------------------------
__global__ void k_zero(int n) {
    int i = blockIdx.x * blockDim.x + threadIdx.x;
    if (i < n) g_cnt[i] = 0;
}

__global__ void k_build(const int* __restrict__ ei, int e, int n) {
    int i = blockIdx.x * blockDim.x + threadIdx.x;
    if (i >= e) return;
    int s = ei[i];
    int d = ei[e + i];
    if ((unsigned)s >= (unsigned)n || (unsigned)d >= (unsigned)n) return;
    int pos = atomicAdd(&g_cnt[d], 1);
    if (pos < CAP) g_bucket[(size_t)d * CAP + pos] = s;
}

__global__ void k_isqrt(int n) {
    int i = blockIdx.x * blockDim.x + threadIdx.x;
    if (i < n) g_isq[i] = rsqrtf((float)g_cnt[i] + 1.0f);
}

// ---------------- GEMM1 partials: g_partf[ks] = x[:, ks-slice] @ W1[ks-slice] -
// grid (n/64, 4); 256 thr. c = t&15 (channel), slot = t>>4 (row slot 0..15);
// thread owns rows slot+16j (j=0..3) for channel c; k-pairs in f32x2.
__global__ void __launch_bounds__(256, 3) k_gemm1(const float* __restrict__ x,
                                                  const float* __restrict__ W1,
                                                  int n) {
    __shared__ __align__(16) float xs[2 * XS_F];             // 32 KB
    __shared__ __align__(16) unsigned long long wt[GC * WT_P]; // 8.5 KB

    int t = threadIdx.x;
    int c = t & 15;
    int slot = t >> 4;
    int ks = blockIdx.y;
    int rb = blockIdx.x * ROWS_B;
    const float4* x4 = (const float4*)x;
    uint32_t xs_sa = (uint32_t)__cvta_generic_to_shared(xs);

    // stage W slice as k-pairs: wt[c][kp] = (W1[k0][c], W1[k0+1][c])
#pragma unroll
    for (int i = 0; i < 4; i++) {
        int idx = t + 256 * i;       // 0..1023
        int cc = idx >> 6, kp = idx & 63;
        int k0 = ks * KPER + 2 * kp;
        union { float2 f; unsigned long long u; } pk;
        pk.f.x = W1[(size_t)k0 * GC + cc];
        pk.f.y = W1[(size_t)(k0 + 1) * GC + cc];
        wt[cc * WT_P + kp] = pk.u;
    }

    // stage x chunk: 64 rows x 16 float4 = 1024 cp.async, 4 per thread
    auto stage = [&](int ch) {
#pragma unroll
        for (int i = 0; i < 4; i++) {
            int idx = t + 256 * i;   // 0..1023
            int r = idx >> 4, f4 = idx & 15;
            int gr = rb + r;
            if (gr >= n) gr = n - 1;
            const float4* src =
                x4 + (size_t)gr * (GK / 4) + ks * (KPER / 4) + ch * (KCH / 4) + f4;
            uint32_t dst = xs_sa + (uint32_t)((ch & 1) * XS_F * 4 +
                                              (r * KCH + 4 * f4) * 4);
            cp_async16(dst, src);
        }
        asm volatile("cp.async.commit_group;" ::: "memory");
    };

    unsigned long long accA[4], accB[4];
#pragma unroll
    for (int j = 0; j < 4; j++) { accA[j] = 0ull; accB[j] = 0ull; }

    stage(0);
    stage(1);
#pragma unroll
    for (int ch = 0; ch < 2; ch++) {
        if (ch == 0)
            asm volatile("cp.async.wait_group 1;" ::: "memory");
        else
            asm volatile("cp.async.wait_group 0;" ::: "memory");
        __syncthreads();

        const float* xb = xs + (ch & 1) * XS_F;
        // 4 sub-chunks of 16 k (8 k-pairs) each
#pragma unroll
        for (int s16 = 0; s16 < 4; s16++) {
            ulonglong2 wreg[4];
            const unsigned long long* wc = wt + c * WT_P + ch * 32 + s16 * 8;
#pragma unroll
            for (int i = 0; i < 4; i++) wreg[i] = *(const ulonglong2*)(wc + 2 * i);
#pragma unroll
            for (int j = 0; j < 4; j++) {
                const float* xr = xb + (slot + 16 * j) * KCH + s16 * 16;
                ulonglong2 xv[4];
#pragma unroll
                for (int i = 0; i < 4; i++)
                    xv[i] = *(const ulonglong2*)(xr + 4 * i);
#pragma unroll
                for (int i = 0; i < 4; i++) {
                    accA[j] = ffma2(xv[i].x, wreg[i].x, accA[j]);
                    accB[j] = ffma2(xv[i].y, wreg[i].y, accB[j]);
                }
            }
        }
    }

    // epilogue: store fp32 partial for this k-slice (no atomics)
#pragma unroll
    for (int j = 0; j < 4; j++) {
        int row = rb + slot + 16 * j;
        if (row < n) {
            unsigned long long a = addf2(accA[j], accB[j]);
            unsigned lo, hi;
            asm("mov.b64 {%0,%1}, %2;" : "=r"(lo), "=r"(hi) : "l"(a));
            g_partf[((size_t)ks * GN + row) * GC + c] =
                __uint_as_float(lo) + __uint_as_float(hi);
        }
    }
}

// -------- combine partial slices -> ht1 (fp16, isq-scaled) -------------------
__global__ void __launch_bounds__(256) k_combine(int n) {
    int idx = blockIdx.x * blockDim.x + threadIdx.x;   // node*4 + quad
    int node = idx >> 2, q = idx & 3;
    if (node >= n) return;
    float4 s = make_float4(0.f, 0.f, 0.f, 0.f);
#pragma unroll
    for (int ksl = 0; ksl < KS; ksl++) {
        const float4* p =
            (const float4*)(g_partf + ((size_t)ksl * GN + node) * GC) + q;
        float4 v = __ldg(p);
        s.x += v.x; s.y += v.y; s.z += v.z; s.w += v.w;
    }
    float sc = g_isq[node];
    union { unsigned long long u; __half2 h[2]; } pk;
    pk.h[0] = __floats2half2_rn(s.x * sc, s.y * sc);
    pk.h[1] = __floats2half2_rn(s.z * sc, s.w * sc);
    *(unsigned long long*)(g_ht1 + (size_t)node * GC + 4 * q) = pk.u;
}

// -------- fused agg(ht1) + layer2 -> ht2 (fp16) ------------------------------
__global__ void __launch_bounds__(256) k_agg_l2(const float* __restrict__ W2,
                                                const float* __restrict__ b1,
                                                int n) {
    __shared__ float sW[GC * GC];
    __shared__ float sb[GC];
    if (threadIdx.x < GC * GC) sW[threadIdx.x] = W2[threadIdx.x];
    if (threadIdx.x < GC) sb[threadIdx.x] = b1[threadIdx.x];
    __syncthreads();

    int w = blockIdx.x * 8 + (threadIdx.x >> 5);
    if (w >= n) return;
    int lane = threadIdx.x & 31;
    int q = lane & 3;
    int es = lane >> 2;
    const uint2* htp = (const uint2*)g_ht1;

    float4 a = (es == 0) ? gat4(htp, w, q) : make_float4(0.f, 0.f, 0.f, 0.f);
    int cnt = min(g_cnt[w], CAP);
    const int* bk = g_bucket + (size_t)w * CAP;

    int i = es;
    int s = (i < cnt) ? __ldg(bk + i) : 0;
    while (i < cnt) {
        int nx = (i + 8 < cnt) ? __ldg(bk + i + 8) : 0;
        float4 v = gat4(htp, s, q);
        a.x += v.x; a.y += v.y; a.z += v.z; a.w += v.w;
        i += 8;
        s = nx;
    }
#pragma unroll
    for (int off = 4; off <= 16; off <<= 1) {
        a.x += __shfl_xor_sync(0xffffffffu, a.x, off);
        a.y += __shfl_xor_sync(0xffffffffu, a.y, off);
        a.z += __shfl_xor_sync(0xffffffffu, a.z, off);
        a.w += __shfl_xor_sync(0xffffffffu, a.w, off);
    }
    float sc = g_isq[w];
    float4 z = make_float4(fmaxf(sc * a.x + sb[4 * q + 0], 0.f),
                           fmaxf(sc * a.y + sb[4 * q + 1], 0.f),
                           fmaxf(sc * a.z + sb[4 * q + 2], 0.f),
                           fmaxf(sc * a.w + sb[4 * q + 3], 0.f));
    float4 o = make_float4(0.f, 0.f, 0.f, 0.f);
#pragma unroll
    for (int kq = 0; kq < 4; kq++) {
        int srcl = (lane & 28) | kq;
        float zk[4];
        zk[0] = __shfl_sync(0xffffffffu, z.x, srcl);
        zk[1] = __shfl_sync(0xffffffffu, z.y, srcl);
        zk[2] = __shfl_sync(0xffffffffu, z.z, srcl);
        zk[3] = __shfl_sync(0xffffffffu, z.w, srcl);
#pragma unroll
        for (int m = 0; m < 4; m++) {
            const float* wr = sW + (4 * kq + m) * GC + 4 * q;
            o.x = fmaf(zk[m], wr[0], o.x);
            o.y = fmaf(zk[m], wr[1], o.y);
            o.z = fmaf(zk[m], wr[2], o.z);
            o.w = fmaf(zk[m], wr[3], o.w);
        }
    }
    if (es == 0) {
        __half2 h0 = __floats2half2_rn(o.x * sc, o.y * sc);
        __half2 h1 = __floats2half2_rn(o.z * sc, o.w * sc);
        union { uint2 u; __half2 h[2]; } pk;
        pk.h[0] = h0; pk.h[1] = h1;
        *(uint2*)(g_ht2 + (size_t)w * GC + 4 * q) = pk.u;
    }
}

// -------- fused agg(ht2) + layer3 -> ht3 (fp32 scalar) -----------------------
__global__ void __launch_bounds__(256) k_agg_l3(const float* __restrict__ W3,
                                                const float* __restrict__ b2,
                                                int n) {
    __shared__ float sW[GC];
    __shared__ float sb[GC];
    if (threadIdx.x < GC) {
        sW[threadIdx.x] = W3[threadIdx.x];
        sb[threadIdx.x] = b2[threadIdx.x];
    }
    __syncthreads();

    int w = blockIdx.x * 8 + (threadIdx.x >> 5);
    if (w >= n) return;
    int lane = threadIdx.x & 31;
    int q = lane & 3;
    int es = lane >> 2;
    const uint2* htp = (const uint2*)g_ht2;

    float4 a = (es == 0) ? gat4(htp, w, q) : make_float4(0.f, 0.f, 0.f, 0.f);
    int cnt = min(g_cnt[w], CAP);
    const int* bk = g_bucket + (size_t)w * CAP;

    int i = es;
    int s = (i < cnt) ? __ldg(bk + i) : 0;
    while (i < cnt) {
        int nx = (i + 8 < cnt) ? __ldg(bk + i + 8) : 0;
        float4 v = gat4(htp, s, q);
        a.x += v.x; a.y += v.y; a.z += v.z; a.w += v.w;
        i += 8;
        s = nx;
    }
#pragma unroll
    for (int off = 4; off <= 16; off <<= 1) {
        a.x += __shfl_xor_sync(0xffffffffu, a.x, off);
        a.y += __shfl_xor_sync(0xffffffffu, a.y, off);
        a.z += __shfl_xor_sync(0xffffffffu, a.z, off);
        a.w += __shfl_xor_sync(0xffffffffu, a.w, off);
    }
    float sc = g_isq[w];
    float p = fmaxf(sc * a.x + sb[4 * q + 0], 0.f) * sW[4 * q + 0]
            + fmaxf(sc * a.y + sb[4 * q + 1], 0.f) * sW[4 * q + 1]
            + fmaxf(sc * a.z + sb[4 * q + 2], 0.f) * sW[4 * q + 2]
            + fmaxf(sc * a.w + sb[4 * q + 3], 0.f) * sW[4 * q + 3];
    p += __shfl_xor_sync(0xffffffffu, p, 1);
    p += __shfl_xor_sync(0xffffffffu, p, 2);
    if (lane == 0) g_ht3[w] = p * sc;
}

// -------- fused agg(ht3) + bias -> out ---------------------------------------
__global__ void __launch_bounds__(256) k_agg_final(const float* __restrict__ b3,
                                                   float* __restrict__ out, int n) {
    int w = blockIdx.x * 8 + (threadIdx.x >> 5);
    if (w >= n) return;
    int lane = threadIdx.x & 31;
    float a = (lane == 0) ? g_ht3[w] : 0.f;
    int cnt = min(g_cnt[w], CAP);
    const int* bk = g_bucket + (size_t)w * CAP;
    for (int i = lane; i < cnt; i += 32) a += __ldg(&g_ht3[__ldg(bk + i)]);
#pragma unroll
    for (int off = 16; off >= 1; off >>= 1)
        a += __shfl_xor_sync(0xffffffffu, a, off);
    if (lane == 0) out[w] = g_isq[w] * a + __ldg(b3);
}

// ---------------- launch -----------------------------------------------------
extern "C" void kernel_launch(void* const* d_in, const int* in_sizes, int n_in,
                              void* d_out, int out_size) {
    const float* x  = (const float*)d_in[0];
    const int*   ei = (const int*)d_in[1];   // int32 edge_index [2, E]
    const float* W1 = (const float*)d_in[2];
    const float* b1 = (const float*)d_in[3];
    const float* W2 = (const float*)d_in[4];
    const float* b2 = (const float*)d_in[5];
    const float* W3 = (const float*)d_in[6];
    const float* b3 = (const float*)d_in[7];
    float* out = (float*)d_out;

    int n = in_sizes[0] / GK;
    int e = in_sizes[1] / 2;
    if (n > GN) n = GN;
    if (e > GE) e = GE;

    int nb = (n + 255) / 256;
    int eb = (e + 255) / 256;
    int wb = (n + 7) / 8;
    int tiles = (n + ROWS_B - 1) / ROWS_B;
    int cb = (4 * n + 255) / 256;

    k_zero<<<nb, 256>>>(n);
    k_build<<<eb, 256>>>(ei, e, n);
    k_isqrt<<<nb, 256>>>(n);
    k_gemm1<<<dim3(tiles, KS), 256>>>(x, W1, n);
    k_combine<<<cb, 256>>>(n);
    k_agg_l2<<<wb, 256>>>(W2, b1, n);
    k_agg_l3<<<wb, 256>>>(W3, b2, n);
    k_agg_final<<<wb, 256>>>(b3, out, n);
}

// round 16
// speedup vs baseline: 1.2312x; 1.2312x over previous
#include <cuda_runtime.h>
#include <cuda_fp16.h>
#include <cstdint>

// 3-layer GCN, bucket-grouped aggregation, fp16 message payloads.
//   ht = (hW)*isq per node (fp16);  acc[d] = ht[d] + sum_{s->d} ht[s] (fp32);
//   next layer input = relu(isq*acc + b). One edge pass builds per-dst buckets.
// GEMM1: W fully staged in smem (k-pair u64, warp-uniform broadcast reads),
// x streamed straight from gmem as ulonglong2 (k-pairs, zero pack movs),
// 2 rows per thread, NO mainloop barriers, 24 warps/SM.
// edge_index arrives as int32 (JAX x64-disabled demotes int64).

#define GN 100000
#define GE 3200000
#define GK 512
#define GC 16
#define CAP 128      // bucket slots per node; P(deg>128) ~ 1e-60

// ---------------- scratch (static device globals) ----------------------------
__device__ __align__(256) float  g_isq[GN];
__device__ __align__(256) __half g_ht1[GN * GC];
__device__ __align__(256) __half g_ht2[GN * GC];
__device__ __align__(256) float  g_ht3[GN];
__device__ __align__(256) int    g_cnt[GN];
__device__ __align__(256) int    g_bucket[(size_t)GN * CAP];  // 51.2 MB

// ---------------- helpers -----------------------------------------------------
__device__ __forceinline__ unsigned long long ffma2(unsigned long long a,
                                                    unsigned long long b,
                                                    unsigned long long c) {
    unsigned long long d;
    asm("fma.rn.f32x2 %0, %1, %2, %3;" : "=l"(d) : "l"(a), "l"(b), "l"(c));
    return d;
}
__device__ __forceinline__ float4 gat4(const uint2* __restrict__ htp, int s, int q) {
    uint2 u = __ldg(htp + (size_t)s * 4 + q);
    __half2 h0 = *(__half2*)&u.x;
    __half2 h1 = *(__half2*)&u.y;
    float2 a = __half22float2(h0), b = __half22float2(h1);
    return make_float4(a.x, a.y, b.x, b.y);
}

// ---------------- prep -------------------------------------------------------
__global__ void k_zero(int n) {
    int i = blockIdx.x * blockDim.x + threadIdx.x;
    if (i < n) g_cnt[i] = 0;
}

__global__ void k_build(const int* __restrict__ ei, int e, int n) {
    int i = blockIdx.x * blockDim.x + threadIdx.x;
    if (i >= e) return;
    int s = ei[i];
    int d = ei[e + i];
    if ((unsigned)s >= (unsigned)n || (unsigned)d >= (unsigned)n) return;
    int pos = atomicAdd(&g_cnt[d], 1);
    if (pos < CAP) g_bucket[(size_t)d * CAP + pos] = s;
}

__global__ void k_isqrt(int n) {
    int i = blockIdx.x * blockDim.x + threadIdx.x;
    if (i < n) g_isq[i] = rsqrtf((float)g_cnt[i] + 1.0f);
}

// ---------------- GEMM1: ht1 = fp16((x @ W1) * isq) --------------------------
// block 128 thr = 256 rows (2 rows/thread: t and t+128). W1 staged ONCE to
// smem as wt[kp][c] = (W1[2kp][c], W1[2kp+1][c]); mainloop has zero barriers.
// acc[c] holds packed (even-k, odd-k) partials; merged in the epilogue.
__global__ void __launch_bounds__(128) k_gemm1(const float* __restrict__ x,
                                               const float* __restrict__ W1,
                                               int n) {
    __shared__ unsigned long long wt[(GK / 2) * GC];  // 32 KB

    int t = threadIdx.x;
    // stage W^T k-pairs: 4096 u64, 32 per thread
#pragma unroll
    for (int i = 0; i < 32; i++) {
        int idx = t + 128 * i;          // 0..4095
        int kp = idx >> 4, c = idx & 15;
        union { float2 f; unsigned long long u; } pk;
        pk.f.x = W1[(size_t)(2 * kp) * GC + c];
        pk.f.y = W1[(size_t)(2 * kp + 1) * GC + c];
        wt[kp * GC + c] = pk.u;
    }
    __syncthreads();

    int row0 = blockIdx.x * 256 + t;
    int row1 = row0 + 128;
    int r0c = row0 < n ? row0 : (n - 1);
    int r1c = row1 < n ? row1 : (n - 1);
    const ulonglong2* xb0 = (const ulonglong2*)(x + (size_t)r0c * GK);
    const ulonglong2* xb1 = (const ulonglong2*)(x + (size_t)r1c * GK);

    unsigned long long acc0[GC], acc1[GC];
#pragma unroll
    for (int c = 0; c < GC; c++) { acc0[c] = 0ull; acc1[c] = 0ull; }

    // mainloop: 128 iterations of 4 k (2 k-pairs); no barriers
#pragma unroll 4
    for (int c4 = 0; c4 < GK / 4; c4++) {
        ulonglong2 xv0 = __ldg(xb0 + c4);   // (kpair0, kpair1) of row0
        ulonglong2 xv1 = __ldg(xb1 + c4);
        const unsigned long long* wr = wt + (2 * c4) * GC;
#pragma unroll
        for (int kp = 0; kp < 2; kp++) {
            unsigned long long xk0 = (kp == 0) ? xv0.x : xv0.y;
            unsigned long long xk1 = (kp == 0) ? xv1.x : xv1.y;
            const unsigned long long* wv = wr + kp * GC;   // uniform -> broadcast
#pragma unroll
            for (int c = 0; c < GC; c++) {
                unsigned long long w = wv[c];
                acc0[c] = ffma2(xk0, w, acc0[c]);
                acc1[c] = ffma2(xk1, w, acc1[c]);
            }
        }
    }

    // epilogue: merge even/odd-k halves, scale, pack fp16, store 32 B/row
    if (row0 < n) {
        float s = g_isq[row0];
        union { uint4 u[2]; __half2 h[8]; } pk;
#pragma unroll
        for (int p = 0; p < 8; p++) {
            unsigned lo0, hi0, lo1, hi1;
            asm("mov.b64 {%0,%1}, %2;" : "=r"(lo0), "=r"(hi0) : "l"(acc0[2 * p]));
            asm("mov.b64 {%0,%1}, %2;" : "=r"(lo1), "=r"(hi1) : "l"(acc0[2 * p + 1]));
            pk.h[p] = __floats2half2_rn(
                (__uint_as_float(lo0) + __uint_as_float(hi0)) * s,
                (__uint_as_float(lo1) + __uint_as_float(hi1)) * s);
        }
        uint4* hp = (uint4*)(g_ht1 + (size_t)row0 * GC);
        hp[0] = pk.u[0];
        hp[1] = pk.u[1];
    }
    if (row1 < n) {
        float s = g_isq[row1];
        union { uint4 u[2]; __half2 h[8]; } pk;
#pragma unroll
        for (int p = 0; p < 8; p++) {
            unsigned lo0, hi0, lo1, hi1;
            asm("mov.b64 {%0,%1}, %2;" : "=r"(lo0), "=r"(hi0) : "l"(acc1[2 * p]));
            asm("mov.b64 {%0,%1}, %2;" : "=r"(lo1), "=r"(hi1) : "l"(acc1[2 * p + 1]));
            pk.h[p] = __floats2half2_rn(
                (__uint_as_float(lo0) + __uint_as_float(hi0)) * s,
                (__uint_as_float(lo1) + __uint_as_float(hi1)) * s);
        }
        uint4* hp = (uint4*)(g_ht1 + (size_t)row1 * GC);
        hp[0] = pk.u[0];
        hp[1] = pk.u[1];
    }
}

// -------- fused agg(ht1) + layer2 -> ht2 (fp16) ------------------------------
__global__ void __launch_bounds__(256) k_agg_l2(const float* __restrict__ W2,
                                                const float* __restrict__ b1,
                                                int n) {
    __shared__ float sW[GC * GC];
    __shared__ float sb[GC];
    if (threadIdx.x < GC * GC) sW[threadIdx.x] = W2[threadIdx.x];
    if (threadIdx.x < GC) sb[threadIdx.x] = b1[threadIdx.x];
    __syncthreads();

    int w = blockIdx.x * 8 + (threadIdx.x >> 5);
    if (w >= n) return;
    int lane = threadIdx.x & 31;
    int q = lane & 3;
    int es = lane >> 2;
    const uint2* htp = (const uint2*)g_ht1;

    float4 a = (es == 0) ? gat4(htp, w, q) : make_float4(0.f, 0.f, 0.f, 0.f);
    int cnt = min(g_cnt[w], CAP);
    const int* bk = g_bucket + (size_t)w * CAP;

    int i = es;
    int s = (i < cnt) ? __ldg(bk + i) : 0;
    while (i < cnt) {
        int nx = (i + 8 < cnt) ? __ldg(bk + i + 8) : 0;
        float4 v = gat4(htp, s, q);
        a.x += v.x; a.y += v.y; a.z += v.z; a.w += v.w;
        i += 8;
        s = nx;
    }
#pragma unroll
    for (int off = 4; off <= 16; off <<= 1) {
        a.x += __shfl_xor_sync(0xffffffffu, a.x, off);
        a.y += __shfl_xor_sync(0xffffffffu, a.y, off);
        a.z += __shfl_xor_sync(0xffffffffu, a.z, off);
        a.w += __shfl_xor_sync(0xffffffffu, a.w, off);
    }
    float sc = g_isq[w];
    float4 z = make_float4(fmaxf(sc * a.x + sb[4 * q + 0], 0.f),
                           fmaxf(sc * a.y + sb[4 * q + 1], 0.f),
                           fmaxf(sc * a.z + sb[4 * q + 2], 0.f),
                           fmaxf(sc * a.w + sb[4 * q + 3], 0.f));
    float4 o = make_float4(0.f, 0.f, 0.f, 0.f);
#pragma unroll
    for (int kq = 0; kq < 4; kq++) {
        int srcl = (lane & 28) | kq;
        float zk[4];
        zk[0] = __shfl_sync(0xffffffffu, z.x, srcl);
        zk[1] = __shfl_sync(0xffffffffu, z.y, srcl);
        zk[2] = __shfl_sync(0xffffffffu, z.z, srcl);
        zk[3] = __shfl_sync(0xffffffffu, z.w, srcl);
#pragma unroll
        for (int m = 0; m < 4; m++) {
            const float* wr = sW + (4 * kq + m) * GC + 4 * q;
            o.x = fmaf(zk[m], wr[0], o.x);
            o.y = fmaf(zk[m], wr[1], o.y);
            o.z = fmaf(zk[m], wr[2], o.z);
            o.w = fmaf(zk[m], wr[3], o.w);
        }
    }
    if (es == 0) {
        __half2 h0 = __floats2half2_rn(o.x * sc, o.y * sc);
        __half2 h1 = __floats2half2_rn(o.z * sc, o.w * sc);
        union { uint2 u; __half2 h[2]; } pk;
        pk.h[0] = h0; pk.h[1] = h1;
        *(uint2*)(g_ht2 + (size_t)w * GC + 4 * q) = pk.u;
    }
}

// -------- fused agg(ht2) + layer3 -> ht3 (fp32 scalar) -----------------------
__global__ void __launch_bounds__(256) k_agg_l3(const float* __restrict__ W3,
                                                const float* __restrict__ b2,
                                                int n) {
    __shared__ float sW[GC];
    __shared__ float sb[GC];
    if (threadIdx.x < GC) {
        sW[threadIdx.x] = W3[threadIdx.x];
        sb[threadIdx.x] = b2[threadIdx.x];
    }
    __syncthreads();

    int w = blockIdx.x * 8 + (threadIdx.x >> 5);
    if (w >= n) return;
    int lane = threadIdx.x & 31;
    int q = lane & 3;
    int es = lane >> 2;
    const uint2* htp = (const uint2*)g_ht2;

    float4 a = (es == 0) ? gat4(htp, w, q) : make_float4(0.f, 0.f, 0.f, 0.f);
    int cnt = min(g_cnt[w], CAP);
    const int* bk = g_bucket + (size_t)w * CAP;

    int i = es;
    int s = (i < cnt) ? __ldg(bk + i) : 0;
    while (i < cnt) {
        int nx = (i + 8 < cnt) ? __ldg(bk + i + 8) : 0;
        float4 v = gat4(htp, s, q);
        a.x += v.x; a.y += v.y; a.z += v.z; a.w += v.w;
        i += 8;
        s = nx;
    }
#pragma unroll
    for (int off = 4; off <= 16; off <<= 1) {
        a.x += __shfl_xor_sync(0xffffffffu, a.x, off);
        a.y += __shfl_xor_sync(0xffffffffu, a.y, off);
        a.z += __shfl_xor_sync(0xffffffffu, a.z, off);
        a.w += __shfl_xor_sync(0xffffffffu, a.w, off);
    }
    float sc = g_isq[w];
    float p = fmaxf(sc * a.x + sb[4 * q + 0], 0.f) * sW[4 * q + 0]
            + fmaxf(sc * a.y + sb[4 * q + 1], 0.f) * sW[4 * q + 1]
            + fmaxf(sc * a.z + sb[4 * q + 2], 0.f) * sW[4 * q + 2]
            + fmaxf(sc * a.w + sb[4 * q + 3], 0.f) * sW[4 * q + 3];
    p += __shfl_xor_sync(0xffffffffu, p, 1);
    p += __shfl_xor_sync(0xffffffffu, p, 2);
    if (lane == 0) g_ht3[w] = p * sc;
}

// -------- fused agg(ht3) + bias -> out ---------------------------------------
__global__ void __launch_bounds__(256) k_agg_final(const float* __restrict__ b3,
                                                   float* __restrict__ out, int n) {
    int w = blockIdx.x * 8 + (threadIdx.x >> 5);
    if (w >= n) return;
    int lane = threadIdx.x & 31;
    float a = (lane == 0) ? g_ht3[w] : 0.f;
    int cnt = min(g_cnt[w], CAP);
    const int* bk = g_bucket + (size_t)w * CAP;
    for (int i = lane; i < cnt; i += 32) a += __ldg(&g_ht3[__ldg(bk + i)]);
#pragma unroll
    for (int off = 16; off >= 1; off >>= 1)
        a += __shfl_xor_sync(0xffffffffu, a, off);
    if (lane == 0) out[w] = g_isq[w] * a + __ldg(b3);
}

// ---------------- launch -----------------------------------------------------
extern "C" void kernel_launch(void* const* d_in, const int* in_sizes, int n_in,
                              void* d_out, int out_size) {
    const float* x  = (const float*)d_in[0];
    const int*   ei = (const int*)d_in[1];   // int32 edge_index [2, E]
    const float* W1 = (const float*)d_in[2];
    const float* b1 = (const float*)d_in[3];
    const float* W2 = (const float*)d_in[4];
    const float* b2 = (const float*)d_in[5];
    const float* W3 = (const float*)d_in[6];
    const float* b3 = (const float*)d_in[7];
    float* out = (float*)d_out;

    int n = in_sizes[0] / GK;
    int e = in_sizes[1] / 2;
    if (n > GN) n = GN;
    if (e > GE) e = GE;

    int nb = (n + 255) / 256;
    int eb = (e + 255) / 256;
    int wb = (n + 7) / 8;

    k_zero<<<nb, 256>>>(n);
    k_build<<<eb, 256>>>(ei, e, n);
    k_isqrt<<<nb, 256>>>(n);
    k_gemm1<<<(n + 255) / 256, 128>>>(x, W1, n);
    k_agg_l2<<<wb, 256>>>(W2, b1, n);
    k_agg_l3<<<wb, 256>>>(W3, b2, n);
    k_agg_final<<<wb, 256>>>(b3, out, n);
}